// round 16
// baseline (speedup 1.0000x reference)
#include <cuda_runtime.h>
#include <cuda_fp16.h>
#include <math.h>
#include <stdint.h>

#define N_NODES  100000
#define N_HEDGES 100000
#define N_INC    3200000
#define N_LINKS  262144
#define C1 128
#define C2 256

#define SCAN_ELEMS 1024
#define SCAN_BLOCKS ((N_NODES + SCAN_ELEMS - 1) / SCAN_ELEMS)   // 98

// ---------------- device scratch (static; no cudaMalloc) ----------------
__device__ int   g_dv_cnt[N_NODES];
__device__ int   g_node_off[N_NODES + 1];
__device__ int   g_edge_off[N_HEDGES + 1];
__device__ int   g_cursor[N_NODES];
__device__ int   g_node_edges[N_INC];
__device__ int   g_blk_sums[SCAN_BLOCKS];
__device__ int   g_blk_offs[SCAN_BLOCKS];
__device__ float g_dvi[N_NODES];    // Dv^{-1/2}
__device__ float g_te[N_HEDGES];
__device__ float g_s[N_NODES];      // s = S*1
__device__ float g_zfc[N_NODES];
__device__ __half g_Xh [(size_t)N_NODES * C1];   // fp16 X, then scaled in place by dvi
__device__ __half g_X2h[(size_t)N_NODES * C1];   // S*X (fp16, GEMM input)
__device__ __half g_th [(size_t)N_NODES * C1];   // dvi * (relu(X2 W1 + s b1) W2) fp16
__device__ __half g_W1T[(size_t)C2 * C1];        // W1^T fp16 [256,128]
__device__ __half g_W2T[(size_t)C1 * C2];        // W2^T fp16 [128,256]
__device__ __half g_Yeh[(size_t)N_HEDGES * C1];  // fp16 Ye rows (both layers, reused)

// ---------------- cp.async helpers ----------------
__device__ __forceinline__ void cp_async16(void* dst, const void* src, bool pred) {
    uint32_t d = (uint32_t)__cvta_generic_to_shared(dst);
    int sz = pred ? 16 : 0;
    asm volatile("cp.async.cg.shared.global [%0], [%1], 16, %2;"
                 :: "r"(d), "l"(src), "r"(sz));
}
#define CP_COMMIT()  asm volatile("cp.async.commit_group;" ::: "memory")
#define CP_WAIT_1()  asm volatile("cp.async.wait_group 1;" ::: "memory")
#define CP_WAIT_0()  asm volatile("cp.async.wait_group 0;" ::: "memory")

// ---------------- setup kernels ----------------
__global__ __launch_bounds__(256)
void count_kernel(const int* __restrict__ inc_v) {
    int i = blockIdx.x * 256 + threadIdx.x;
    if (i < N_INC) atomicAdd(&g_dv_cnt[inc_v[i]], 1);
}

__global__ __launch_bounds__(256)
void node_scan_phase1() {
    int b = blockIdx.x, t = threadIdx.x;
    int base = b * SCAN_ELEMS + t * 4;
    int s = 0;
    #pragma unroll
    for (int k = 0; k < 4; k++) { int i = base + k; if (i < N_NODES) s += g_dv_cnt[i]; }
    __shared__ int sh[256];
    sh[t] = s; __syncthreads();
    #pragma unroll
    for (int d = 128; d > 0; d >>= 1) { if (t < d) sh[t] += sh[t + d]; __syncthreads(); }
    if (t == 0) g_blk_sums[b] = sh[0];
}

__global__ __launch_bounds__(128)
void node_scan_phase2() {
    int t = threadIdx.x;
    __shared__ int sh[128];
    int v = (t < SCAN_BLOCKS) ? g_blk_sums[t] : 0;
    sh[t] = v; __syncthreads();
    #pragma unroll
    for (int d = 1; d < 128; d <<= 1) {
        int x = (t >= d) ? sh[t - d] : 0; __syncthreads(); sh[t] += x; __syncthreads();
    }
    if (t < SCAN_BLOCKS) g_blk_offs[t] = sh[t] - v;
    if (t == 127) g_node_off[N_NODES] = sh[127];
}

__global__ __launch_bounds__(256)
void node_scan_phase3() {
    int b = blockIdx.x, t = threadIdx.x;
    int base = b * SCAN_ELEMS + t * 4;
    int c[4]; int s = 0;
    #pragma unroll
    for (int k = 0; k < 4; k++) { int i = base + k; c[k] = (i < N_NODES) ? g_dv_cnt[i] : 0; s += c[k]; }
    __shared__ int sh[256];
    sh[t] = s; __syncthreads();
    #pragma unroll
    for (int d = 1; d < 256; d <<= 1) {
        int x = (t >= d) ? sh[t - d] : 0; __syncthreads(); sh[t] += x; __syncthreads();
    }
    int run = g_blk_offs[b] + sh[t] - s;
    #pragma unroll
    for (int k = 0; k < 4; k++) {
        int i = base + k;
        if (i < N_NODES) {
            g_node_off[i] = run; run += c[k];
            g_dvi[i] = (c[k] > 0) ? rsqrtf((float)c[k]) : 0.0f;
        }
    }
}

__global__ __launch_bounds__(256)
void edge_off_kernel(const int* __restrict__ inc_e) {
    int e = blockIdx.x * 256 + threadIdx.x;
    if (e > N_HEDGES) return;
    int lo = 0, hi = N_INC;
    while (lo < hi) { int mid = (lo + hi) >> 1; if (inc_e[mid] < e) lo = mid + 1; else hi = mid; }
    g_edge_off[e] = lo;
}

__global__ __launch_bounds__(256)
void build_csr_kernel(const int* __restrict__ inc_v, const int* __restrict__ inc_e) {
    int i = blockIdx.x * 256 + threadIdx.x;
    if (i < N_INC) {
        int v = inc_v[i];
        int pos = g_node_off[v] + atomicAdd(&g_cursor[v], 1);
        g_node_edges[pos] = inc_e[i];
    }
}

__global__ __launch_bounds__(256)
void te_kernel(const int* __restrict__ inc_v) {
    int e = blockIdx.x * 256 + threadIdx.x;
    if (e >= N_HEDGES) return;
    int b = g_edge_off[e], en = g_edge_off[e + 1];
    float sum = 0.0f;
    for (int i = b; i < en; i++) sum += g_dvi[inc_v[i]];
    float dei = (en > b) ? 1.0f / (float)(en - b) : 0.0f;
    g_te[e] = dei * sum;
}

__global__ __launch_bounds__(256)
void s_kernel() {
    int v = blockIdx.x * 256 + threadIdx.x;
    if (v >= N_NODES) return;
    int b = g_node_off[v], en = g_node_off[v + 1];
    float sum = 0.0f;
    for (int j = b; j < en; j++) sum += g_te[g_node_edges[j]];
    g_s[v] = g_dvi[v] * sum;
}

__global__ __launch_bounds__(256)
void wt_kernel(const float* __restrict__ W, __half* __restrict__ out, int K, int N) {
    int i = blockIdx.x * 256 + threadIdx.x;
    if (i < K * N) {
        int n = i / K, k = i % K;
        out[i] = __float2half(W[k * N + n]);
    }
}

// pure convert X fp32 -> fp16 (no scaling; independent of counts)
__global__ __launch_bounds__(256)
void x_to_h_kernel(const float* __restrict__ X) {
    int i = blockIdx.x * 256 + threadIdx.x;          // half2 index
    int n = (N_NODES * C1) >> 1;
    if (i < n) {
        float2 v = *(const float2*)(X + i * 2);
        *((__half2*)g_Xh + i) = __floats2half2_rn(v.x, v.y);
    }
}

// in-place scale: Xh[v,:] *= dvi(cnt[v]).  Warp per node.
__global__ __launch_bounds__(256)
void scale_xh_kernel() {
    int v = (blockIdx.x * 256 + threadIdx.x) >> 5;
    if (v >= N_NODES) return;
    int lane = threadIdx.x & 31;
    int c = g_dv_cnt[v];
    float dvi = (c > 0) ? rsqrtf((float)c) : 0.0f;
    __half2* p = (__half2*)(g_Xh + (size_t)v * C1 + lane * 4);
    uint2 d = *(uint2*)p;
    float2 f0 = __half22float2(*(__half2*)&d.x);
    float2 f1 = __half22float2(*(__half2*)&d.y);
    uint2 o;
    ((__half2*)&o)[0] = __floats2half2_rn(f0.x * dvi, f0.y * dvi);
    ((__half2*)&o)[1] = __floats2half2_rn(f1.x * dvi, f1.y * dvi);
    *(uint2*)p = o;
}

// ---------------- gathers: warp/edge(node), 16 lanes x 8ch, 4 incid per half-warp iter ----------------
__device__ __forceinline__ void accum_u4(float* a, uint4 x) {
    const __half2* hx = (const __half2*)&x;
    float2 f0 = __half22float2(hx[0]);
    float2 f1 = __half22float2(hx[1]);
    float2 f2 = __half22float2(hx[2]);
    float2 f3 = __half22float2(hx[3]);
    a[0] += f0.x; a[1] += f0.y; a[2] += f1.x; a[3] += f1.y;
    a[4] += f2.x; a[5] += f2.y; a[6] += f3.x; a[7] += f3.y;
}

__device__ __forceinline__ void gather_rows(float* a, const int* __restrict__ idx,
                                            int b, int e, int half, int li,
                                            const __half* __restrict__ rows) {
    int i = b + half;
    for (; i + 6 < e; i += 8) {
        int u0 = idx[i], u1 = idx[i + 2], u2 = idx[i + 4], u3 = idx[i + 6];
        uint4 x0 = *(const uint4*)(rows + (size_t)u0 * C1 + li * 8);
        uint4 x1 = *(const uint4*)(rows + (size_t)u1 * C1 + li * 8);
        uint4 x2 = *(const uint4*)(rows + (size_t)u2 * C1 + li * 8);
        uint4 x3 = *(const uint4*)(rows + (size_t)u3 * C1 + li * 8);
        accum_u4(a, x0); accum_u4(a, x1); accum_u4(a, x2); accum_u4(a, x3);
    }
    for (; i < e; i += 2) {
        uint4 x = *(const uint4*)(rows + (size_t)idx[i] * C1 + li * 8);
        accum_u4(a, x);
    }
}

// Yeh[e] = (1/deg_e) * sum rows[u]   (rows already carry their dvi factor)
__global__ __launch_bounds__(256)
void edge_agg_kernel(const __half* __restrict__ rows, const int* __restrict__ inc_v) {
    int w = (blockIdx.x * 256 + threadIdx.x) >> 5;
    if (w >= N_HEDGES) return;
    int lane = threadIdx.x & 31;
    int half = lane >> 4, li = lane & 15;
    int b = g_edge_off[w], e = g_edge_off[w + 1];
    float a[8] = {0.f, 0.f, 0.f, 0.f, 0.f, 0.f, 0.f, 0.f};
    gather_rows(a, inc_v, b, e, half, li, rows);
    #pragma unroll
    for (int r = 0; r < 8; r++) a[r] += __shfl_down_sync(0xffffffffu, a[r], 16);
    if (half == 0) {
        float d = (e > b) ? 1.0f / (float)(e - b) : 0.0f;
        uint4 o;
        ((__half2*)&o)[0] = __floats2half2_rn(a[0] * d, a[1] * d);
        ((__half2*)&o)[1] = __floats2half2_rn(a[2] * d, a[3] * d);
        ((__half2*)&o)[2] = __floats2half2_rn(a[4] * d, a[5] * d);
        ((__half2*)&o)[3] = __floats2half2_rn(a[6] * d, a[7] * d);
        *(uint4*)(g_Yeh + (size_t)w * C1 + li * 8) = o;
    }
}

// Xout[v,:] = dvi[v] * sum_e Yeh[e,:]
__global__ __launch_bounds__(256)
void node_agg_h_kernel(__half* __restrict__ Xout) {
    int v = (blockIdx.x * 256 + threadIdx.x) >> 5;
    if (v >= N_NODES) return;
    int lane = threadIdx.x & 31;
    int half = lane >> 4, li = lane & 15;
    int b = g_node_off[v], e = g_node_off[v + 1];
    float a[8] = {0.f, 0.f, 0.f, 0.f, 0.f, 0.f, 0.f, 0.f};
    gather_rows(a, g_node_edges, b, e, half, li, g_Yeh);
    #pragma unroll
    for (int r = 0; r < 8; r++) a[r] += __shfl_down_sync(0xffffffffu, a[r], 16);
    if (half == 0) {
        float d = g_dvi[v];
        uint4 o;
        ((__half2*)&o)[0] = __floats2half2_rn(a[0] * d, a[1] * d);
        ((__half2*)&o)[1] = __floats2half2_rn(a[2] * d, a[3] * d);
        ((__half2*)&o)[2] = __floats2half2_rn(a[4] * d, a[5] * d);
        ((__half2*)&o)[3] = __floats2half2_rn(a[6] * d, a[7] * d);
        *(uint4*)(Xout + (size_t)v * C1 + li * 8) = o;
    }
}

// zfc[v] = sum_c relu(dvi[v]*agg_c + s[v]*b2[c]) * fcW[c]
__global__ __launch_bounds__(256)
void node_agg_final_kernel(const float* __restrict__ b2, const float* __restrict__ fcW) {
    int v = (blockIdx.x * 256 + threadIdx.x) >> 5;
    if (v >= N_NODES) return;
    int lane = threadIdx.x & 31;
    int half = lane >> 4, li = lane & 15;
    int b = g_node_off[v], e = g_node_off[v + 1];
    float a[8] = {0.f, 0.f, 0.f, 0.f, 0.f, 0.f, 0.f, 0.f};
    gather_rows(a, g_node_edges, b, e, half, li, g_Yeh);
    #pragma unroll
    for (int r = 0; r < 8; r++) a[r] += __shfl_down_sync(0xffffffffu, a[r], 16);

    float p = 0.0f;
    if (half == 0) {
        float d  = g_dvi[v];
        float sv = g_s[v];
        float4 bb0 = *(const float4*)(b2 + li * 8);
        float4 bb1 = *(const float4*)(b2 + li * 8 + 4);
        float4 fw0 = *(const float4*)(fcW + li * 8);
        float4 fw1 = *(const float4*)(fcW + li * 8 + 4);
        p += fmaxf(fmaf(d, a[0], sv * bb0.x), 0.f) * fw0.x;
        p += fmaxf(fmaf(d, a[1], sv * bb0.y), 0.f) * fw0.y;
        p += fmaxf(fmaf(d, a[2], sv * bb0.z), 0.f) * fw0.z;
        p += fmaxf(fmaf(d, a[3], sv * bb0.w), 0.f) * fw0.w;
        p += fmaxf(fmaf(d, a[4], sv * bb1.x), 0.f) * fw1.x;
        p += fmaxf(fmaf(d, a[5], sv * bb1.y), 0.f) * fw1.y;
        p += fmaxf(fmaf(d, a[6], sv * bb1.z), 0.f) * fw1.z;
        p += fmaxf(fmaf(d, a[7], sv * bb1.w), 0.f) * fw1.w;
    }
    #pragma unroll
    for (int o = 8; o > 0; o >>= 1) p += __shfl_down_sync(0xffffffffu, p, o);
    if (lane == 0) g_zfc[v] = p;
}

// ---------------- fused GEMM: th = dvi * (relu(X2@W1 + s*b1) @ W2) ----------------
#define FS_X2 69632
#define FS_W2 104448
#define FUSED_SMEM 172032
#define W1S 136
#define X2S 136
#define HS  264
#define W2S 264

__global__ __launch_bounds__(256)
void fused_gemm_kernel(const __half* __restrict__ X2, const __half* __restrict__ W1T,
                       const __half* __restrict__ W2T, int M,
                       const float* __restrict__ s, const float* __restrict__ b1,
                       const float* __restrict__ dvi, __half* __restrict__ th) {
    extern __shared__ char sm[];
    __half* W1s = (__half*)sm;             // also hs
    __half* X2s = (__half*)(sm + FS_X2);
    __half* W2s = (__half*)(sm + FS_W2);

    int tid = threadIdx.x;
    int wid = tid >> 5, lane = tid & 31;
    int warp_m = wid >> 2;
    int warp_n = wid & 3;
    int gid = lane >> 2;
    int tig = lane & 3;
    int blockRow = blockIdx.x * 128;

    #pragma unroll
    for (int t = 0; t < 8; t++) {
        int idx = tid + t * 256;
        int r = idx >> 4, c = (idx & 15) << 3;
        int grow = blockRow + r;
        bool p = grow < M;
        cp_async16(X2s + r * X2S + c, X2 + (size_t)(p ? grow : 0) * C1 + c, p);
    }
    #pragma unroll
    for (int t = 0; t < 16; t++) {
        int idx = tid + t * 256;
        int r = idx >> 4, c = (idx & 15) << 3;
        cp_async16(W1s + r * W1S + c, W1T + (size_t)r * C1 + c, true);
    }
    CP_COMMIT();
    #pragma unroll
    for (int t = 0; t < 16; t++) {
        int idx = tid + t * 256;
        int r = idx >> 5, c = (idx & 31) << 3;
        cp_async16(W2s + r * W2S + c, W2T + (size_t)r * C2 + c, true);
    }
    CP_COMMIT();
    CP_WAIT_1();
    __syncthreads();

    uint32_t hreg[2][4][4][2];
    #pragma unroll
    for (int nh = 0; nh < 2; nh++) {
        float acc[4][4][4];
        #pragma unroll
        for (int i = 0; i < 4; i++)
            #pragma unroll
            for (int j = 0; j < 4; j++)
                #pragma unroll
                for (int r = 0; r < 4; r++) acc[i][j][r] = 0.f;

        #pragma unroll
        for (int k16 = 0; k16 < C1; k16 += 16) {
            uint32_t af[4][4];
            #pragma unroll
            for (int mt = 0; mt < 4; mt++) {
                int rbase = warp_m * 64 + mt * 16;
                const __half* p0 = X2s + (rbase + gid) * X2S + k16 + tig * 2;
                const __half* p1 = X2s + (rbase + gid + 8) * X2S + k16 + tig * 2;
                af[mt][0] = *(const uint32_t*)p0;
                af[mt][1] = *(const uint32_t*)p1;
                af[mt][2] = *(const uint32_t*)(p0 + 8);
                af[mt][3] = *(const uint32_t*)(p1 + 8);
            }
            uint32_t bf[4][2];
            #pragma unroll
            for (int nt = 0; nt < 4; nt++) {
                int nrow = nh * 128 + warp_n * 32 + nt * 8 + gid;
                const __half* p = W1s + nrow * W1S + k16 + tig * 2;
                bf[nt][0] = *(const uint32_t*)p;
                bf[nt][1] = *(const uint32_t*)(p + 8);
            }
            #pragma unroll
            for (int mt = 0; mt < 4; mt++)
                #pragma unroll
                for (int nt = 0; nt < 4; nt++) {
                    asm volatile(
                        "mma.sync.aligned.m16n8k16.row.col.f32.f16.f16.f32 "
                        "{%0,%1,%2,%3}, {%4,%5,%6,%7}, {%8,%9}, {%0,%1,%2,%3};"
                        : "+f"(acc[mt][nt][0]), "+f"(acc[mt][nt][1]),
                          "+f"(acc[mt][nt][2]), "+f"(acc[mt][nt][3])
                        : "r"(af[mt][0]), "r"(af[mt][1]), "r"(af[mt][2]), "r"(af[mt][3]),
                          "r"(bf[nt][0]), "r"(bf[nt][1]));
                }
        }
        #pragma unroll
        for (int mt = 0; mt < 4; mt++) {
            #pragma unroll
            for (int hf = 0; hf < 2; hf++) {
                int row = blockRow + warp_m * 64 + mt * 16 + gid + hf * 8;
                float rs = (row < M) ? s[row] : 0.f;
                #pragma unroll
                for (int nt = 0; nt < 4; nt++) {
                    int col = nh * 128 + warp_n * 32 + nt * 8 + tig * 2;
                    float v0 = fmaxf(fmaf(rs, b1[col],     acc[mt][nt][hf * 2 + 0]), 0.f);
                    float v1 = fmaxf(fmaf(rs, b1[col + 1], acc[mt][nt][hf * 2 + 1]), 0.f);
                    __half2 h2 = __floats2half2_rn(v0, v1);
                    hreg[nh][mt][nt][hf] = *(uint32_t*)&h2;
                }
            }
        }
    }
    __syncthreads();

    #pragma unroll
    for (int nh = 0; nh < 2; nh++)
        #pragma unroll
        for (int mt = 0; mt < 4; mt++)
            #pragma unroll
            for (int hf = 0; hf < 2; hf++) {
                int rloc = warp_m * 64 + mt * 16 + gid + hf * 8;
                #pragma unroll
                for (int nt = 0; nt < 4; nt++) {
                    int col = nh * 128 + warp_n * 32 + nt * 8 + tig * 2;
                    *(uint32_t*)(W1s + rloc * HS + col) = hreg[nh][mt][nt][hf];
                }
            }
    CP_WAIT_0();
    __syncthreads();

    float acc2[4][4][4];
    #pragma unroll
    for (int i = 0; i < 4; i++)
        #pragma unroll
        for (int j = 0; j < 4; j++)
            #pragma unroll
            for (int r = 0; r < 4; r++) acc2[i][j][r] = 0.f;

    #pragma unroll
    for (int k16 = 0; k16 < C2; k16 += 16) {
        uint32_t af[4][4];
        #pragma unroll
        for (int mt = 0; mt < 4; mt++) {
            int rbase = warp_m * 64 + mt * 16;
            const __half* p0 = W1s + (rbase + gid) * HS + k16 + tig * 2;
            const __half* p1 = W1s + (rbase + gid + 8) * HS + k16 + tig * 2;
            af[mt][0] = *(const uint32_t*)p0;
            af[mt][1] = *(const uint32_t*)p1;
            af[mt][2] = *(const uint32_t*)(p0 + 8);
            af[mt][3] = *(const uint32_t*)(p1 + 8);
        }
        uint32_t bf[4][2];
        #pragma unroll
        for (int nt = 0; nt < 4; nt++) {
            int nrow = warp_n * 32 + nt * 8 + gid;
            const __half* p = W2s + nrow * W2S + k16 + tig * 2;
            bf[nt][0] = *(const uint32_t*)p;
            bf[nt][1] = *(const uint32_t*)(p + 8);
        }
        #pragma unroll
        for (int mt = 0; mt < 4; mt++)
            #pragma unroll
            for (int nt = 0; nt < 4; nt++) {
                asm volatile(
                    "mma.sync.aligned.m16n8k16.row.col.f32.f16.f16.f32 "
                    "{%0,%1,%2,%3}, {%4,%5,%6,%7}, {%8,%9}, {%0,%1,%2,%3};"
                    : "+f"(acc2[mt][nt][0]), "+f"(acc2[mt][nt][1]),
                      "+f"(acc2[mt][nt][2]), "+f"(acc2[mt][nt][3])
                    : "r"(af[mt][0]), "r"(af[mt][1]), "r"(af[mt][2]), "r"(af[mt][3]),
                      "r"(bf[nt][0]), "r"(bf[nt][1]));
            }
    }

    #pragma unroll
    for (int mt = 0; mt < 4; mt++) {
        #pragma unroll
        for (int hf = 0; hf < 2; hf++) {
            int row = blockRow + warp_m * 64 + mt * 16 + gid + hf * 8;
            if (row >= M) continue;
            float dv = dvi[row];
            #pragma unroll
            for (int nt = 0; nt < 4; nt++) {
                int col = warp_n * 32 + nt * 8 + tig * 2;
                *(__half2*)(th + (size_t)row * C1 + col) =
                    __floats2half2_rn(acc2[mt][nt][hf * 2 + 0] * dv,
                                      acc2[mt][nt][hf * 2 + 1] * dv);
            }
        }
    }
}

// ---------------- link scoring ----------------
__global__ __launch_bounds__(256)
void link_kernel(const int* __restrict__ link, const float* __restrict__ fcb,
                 float* __restrict__ out) {
    int i = blockIdx.x * 256 + threadIdx.x;
    if (i >= N_LINKS) return;
    int a = link[2 * i], b = link[2 * i + 1];
    float x = (g_zfc[a] + g_zfc[b]) * 0.5f + fcb[0];
    out[i] = 1.0f / (1.0f + __expf(-x));
}

// ---------------- launch ----------------
extern "C" void kernel_launch(void* const* d_in, const int* in_sizes, int n_in,
                              void* d_out, int out_size) {
    const float* X    = (const float*)d_in[0];
    const float* W1   = (const float*)d_in[1];
    const float* b1   = (const float*)d_in[2];
    const float* W2   = (const float*)d_in[3];
    const float* b2   = (const float*)d_in[4];
    const float* fcW  = (const float*)d_in[5];
    const float* fcb  = (const float*)d_in[6];
    const int*   incv = (const int*)d_in[7];
    const int*   ince = (const int*)d_in[8];
    const int*   link = (const int*)d_in[9];
    float* out = (float*)d_out;

    static float*  p_s      = nullptr;
    static float*  p_dvi    = nullptr;
    static __half* p_Xh     = nullptr;
    static __half* p_X2h    = nullptr;
    static __half* p_th     = nullptr;
    static __half* p_W1T    = nullptr;
    static __half* p_W2T    = nullptr;
    static int*    p_dv_cnt = nullptr;
    static int*    p_cursor = nullptr;
    static cudaStream_t s2 = nullptr, s3 = nullptr;
    static cudaEvent_t evFork = nullptr, evB = nullptr, evConv = nullptr,
                       evCount = nullptr, evC = nullptr, evW2 = nullptr;
    if (!p_s) {
        cudaGetSymbolAddress((void**)&p_s,      g_s);
        cudaGetSymbolAddress((void**)&p_dvi,    g_dvi);
        cudaGetSymbolAddress((void**)&p_Xh,     g_Xh);
        cudaGetSymbolAddress((void**)&p_X2h,    g_X2h);
        cudaGetSymbolAddress((void**)&p_th,     g_th);
        cudaGetSymbolAddress((void**)&p_W1T,    g_W1T);
        cudaGetSymbolAddress((void**)&p_W2T,    g_W2T);
        cudaGetSymbolAddress((void**)&p_dv_cnt, g_dv_cnt);
        cudaGetSymbolAddress((void**)&p_cursor, g_cursor);
        cudaStreamCreateWithFlags(&s2, cudaStreamNonBlocking);
        cudaStreamCreateWithFlags(&s3, cudaStreamNonBlocking);
        cudaEventCreateWithFlags(&evFork,  cudaEventDisableTiming);
        cudaEventCreateWithFlags(&evB,     cudaEventDisableTiming);
        cudaEventCreateWithFlags(&evConv,  cudaEventDisableTiming);
        cudaEventCreateWithFlags(&evCount, cudaEventDisableTiming);
        cudaEventCreateWithFlags(&evC,     cudaEventDisableTiming);
        cudaEventCreateWithFlags(&evW2,    cudaEventDisableTiming);
        cudaFuncSetAttribute(fused_gemm_kernel,
                             cudaFuncAttributeMaxDynamicSharedMemorySize, FUSED_SMEM);
    }

    const int TPB = 256;
    int inc_blocks    = (N_INC + TPB - 1) / TPB;
    int node_blocks   = (N_NODES + TPB - 1) / TPB;
    int edge_blocks   = (N_HEDGES + 1 + TPB - 1) / TPB;
    int warp_blocks_e = (N_HEDGES * 32 + TPB - 1) / TPB;
    int warp_blocks_n = (N_NODES * 32 + TPB - 1) / TPB;
    int wt_blocks     = (C1 * C2 + TPB - 1) / TPB;
    int xh_blocks     = ((N_NODES * C1 / 2) + TPB - 1) / TPB;
    int gemm_rows     = (N_NODES + 127) / 128;   // 782

    // ---- branch B (s2): X convert (no count dep!), edge offsets, weight transposes ----
    cudaEventRecord(evFork, 0);
    cudaStreamWaitEvent(s2, evFork, 0);
    x_to_h_kernel<<<xh_blocks, TPB, 0, s2>>>(X);
    cudaEventRecord(evConv, s2);
    edge_off_kernel<<<edge_blocks, TPB, 0, s2>>>(ince);
    cudaEventRecord(evB, s2);
    wt_kernel<<<wt_blocks, TPB, 0, s2>>>(W1, p_W1T, C1, C2);
    wt_kernel<<<wt_blocks, TPB, 0, s2>>>(W2, p_W2T, C2, C1);
    cudaEventRecord(evW2, s2);

    // ---- main: zero counts (memset) -> count -> in-place dvi scale -> edge_agg1 ----
    cudaMemsetAsync(p_dv_cnt, 0, N_NODES * sizeof(int), 0);
    count_kernel<<<inc_blocks, TPB>>>(incv);
    cudaEventRecord(evCount, 0);
    cudaStreamWaitEvent(0, evConv, 0);
    scale_xh_kernel<<<warp_blocks_n, TPB>>>();
    cudaStreamWaitEvent(0, evB, 0);
    edge_agg_kernel<<<warp_blocks_e, TPB>>>(p_Xh, incv);

    // ---- branch C (s3): cursor memset + scan + csr + te + s, hidden under edge_agg1 ----
    cudaMemsetAsync(p_cursor, 0, N_NODES * sizeof(int), s3);
    cudaStreamWaitEvent(s3, evCount, 0);
    cudaStreamWaitEvent(s3, evB, 0);
    node_scan_phase1<<<SCAN_BLOCKS, TPB, 0, s3>>>();
    node_scan_phase2<<<1, 128, 0, s3>>>();
    node_scan_phase3<<<SCAN_BLOCKS, TPB, 0, s3>>>();
    build_csr_kernel<<<inc_blocks, TPB, 0, s3>>>(incv, ince);
    te_kernel<<<node_blocks, TPB, 0, s3>>>(incv);
    s_kernel<<<node_blocks, TPB, 0, s3>>>();
    cudaEventRecord(evC, s3);

    // ---- main: node agg, fused GEMM, layer 2, output ----
    cudaStreamWaitEvent(0, evC, 0);
    node_agg_h_kernel<<<warp_blocks_n, TPB>>>(p_X2h);
    cudaStreamWaitEvent(0, evW2, 0);
    fused_gemm_kernel<<<gemm_rows, 256, FUSED_SMEM>>>(p_X2h, p_W1T, p_W2T,
                                                      N_NODES, p_s, b1, p_dvi, p_th);
    edge_agg_kernel<<<warp_blocks_e, TPB>>>(p_th, incv);
    node_agg_final_kernel<<<warp_blocks_n, TPB>>>(b2, fcW);
    link_kernel<<<(N_LINKS + TPB - 1) / TPB, TPB>>>(link, fcb, out);
    (void)in_sizes; (void)n_in; (void)out_size;
}

// round 17
// speedup vs baseline: 1.0302x; 1.0302x over previous
#include <cuda_runtime.h>
#include <cuda_fp16.h>
#include <math.h>
#include <stdint.h>

#define N_NODES  100000
#define N_HEDGES 100000
#define N_INC    3200000
#define N_LINKS  262144
#define C1 128
#define C2 256

#define SCAN_ELEMS 1024
#define SCAN_BLOCKS ((N_NODES + SCAN_ELEMS - 1) / SCAN_ELEMS)   // 98

// ---------------- device scratch (static; no cudaMalloc) ----------------
__device__ int   g_dv_cnt[N_NODES];
__device__ int   g_node_off[N_NODES + 1];
__device__ int   g_edge_off[N_HEDGES + 1];
__device__ int   g_cursor[N_NODES];
__device__ int   g_node_edges[N_INC];
__device__ int   g_blk_sums[SCAN_BLOCKS];
__device__ int   g_blk_offs[SCAN_BLOCKS];
__device__ float g_dvi[N_NODES];    // Dv^{-1/2}
__device__ float g_te[N_HEDGES];
__device__ float g_s[N_NODES];      // s = S*1
__device__ float g_zfc[N_NODES];
__device__ __half g_Xh [(size_t)N_NODES * C1];   // dvi * X  (fp16, pre-scaled)
__device__ __half g_X2h[(size_t)N_NODES * C1];   // S*X (fp16, GEMM input)
__device__ __half g_th [(size_t)N_NODES * C1];   // dvi * (relu(X2 W1 + s b1) W2) fp16
__device__ __half g_W1T[(size_t)C2 * C1];        // W1^T fp16 [256,128]
__device__ __half g_W2T[(size_t)C1 * C2];        // W2^T fp16 [128,256]
__device__ __half g_Yeh[(size_t)N_HEDGES * C1];  // fp16 Ye rows (both layers, reused)

// ---------------- cp.async helpers ----------------
__device__ __forceinline__ void cp_async16(void* dst, const void* src, bool pred) {
    uint32_t d = (uint32_t)__cvta_generic_to_shared(dst);
    int sz = pred ? 16 : 0;
    asm volatile("cp.async.cg.shared.global [%0], [%1], 16, %2;"
                 :: "r"(d), "l"(src), "r"(sz));
}
#define CP_COMMIT()  asm volatile("cp.async.commit_group;" ::: "memory")
#define CP_WAIT_1()  asm volatile("cp.async.wait_group 1;" ::: "memory")
#define CP_WAIT_0()  asm volatile("cp.async.wait_group 0;" ::: "memory")

// ---------------- setup kernels ----------------
__global__ __launch_bounds__(256)
void zero_counts_kernel() {
    int i = blockIdx.x * 256 + threadIdx.x;
    if (i < N_NODES) { g_dv_cnt[i] = 0; g_cursor[i] = 0; }
}

__global__ __launch_bounds__(256)
void count_kernel(const int* __restrict__ inc_v) {
    int i = blockIdx.x * 256 + threadIdx.x;
    if (i < N_INC) atomicAdd(&g_dv_cnt[inc_v[i]], 1);
}

__global__ __launch_bounds__(256)
void node_scan_phase1() {
    int b = blockIdx.x, t = threadIdx.x;
    int base = b * SCAN_ELEMS + t * 4;
    int s = 0;
    #pragma unroll
    for (int k = 0; k < 4; k++) { int i = base + k; if (i < N_NODES) s += g_dv_cnt[i]; }
    __shared__ int sh[256];
    sh[t] = s; __syncthreads();
    #pragma unroll
    for (int d = 128; d > 0; d >>= 1) { if (t < d) sh[t] += sh[t + d]; __syncthreads(); }
    if (t == 0) g_blk_sums[b] = sh[0];
}

__global__ __launch_bounds__(128)
void node_scan_phase2() {
    int t = threadIdx.x;
    __shared__ int sh[128];
    int v = (t < SCAN_BLOCKS) ? g_blk_sums[t] : 0;
    sh[t] = v; __syncthreads();
    #pragma unroll
    for (int d = 1; d < 128; d <<= 1) {
        int x = (t >= d) ? sh[t - d] : 0; __syncthreads(); sh[t] += x; __syncthreads();
    }
    if (t < SCAN_BLOCKS) g_blk_offs[t] = sh[t] - v;
    if (t == 127) g_node_off[N_NODES] = sh[127];
}

__global__ __launch_bounds__(256)
void node_scan_phase3() {
    int b = blockIdx.x, t = threadIdx.x;
    int base = b * SCAN_ELEMS + t * 4;
    int c[4]; int s = 0;
    #pragma unroll
    for (int k = 0; k < 4; k++) { int i = base + k; c[k] = (i < N_NODES) ? g_dv_cnt[i] : 0; s += c[k]; }
    __shared__ int sh[256];
    sh[t] = s; __syncthreads();
    #pragma unroll
    for (int d = 1; d < 256; d <<= 1) {
        int x = (t >= d) ? sh[t - d] : 0; __syncthreads(); sh[t] += x; __syncthreads();
    }
    int run = g_blk_offs[b] + sh[t] - s;
    #pragma unroll
    for (int k = 0; k < 4; k++) {
        int i = base + k;
        if (i < N_NODES) {
            g_node_off[i] = run; run += c[k];
            g_dvi[i] = (c[k] > 0) ? rsqrtf((float)c[k]) : 0.0f;
        }
    }
}

__global__ __launch_bounds__(256)
void edge_off_kernel(const int* __restrict__ inc_e) {
    int e = blockIdx.x * 256 + threadIdx.x;
    if (e > N_HEDGES) return;
    int lo = 0, hi = N_INC;
    while (lo < hi) { int mid = (lo + hi) >> 1; if (inc_e[mid] < e) lo = mid + 1; else hi = mid; }
    g_edge_off[e] = lo;
}

__global__ __launch_bounds__(256)
void build_csr_kernel(const int* __restrict__ inc_v, const int* __restrict__ inc_e) {
    int i = blockIdx.x * 256 + threadIdx.x;
    if (i < N_INC) {
        int v = inc_v[i];
        int pos = g_node_off[v] + atomicAdd(&g_cursor[v], 1);
        g_node_edges[pos] = inc_e[i];
    }
}

__global__ __launch_bounds__(256)
void te_kernel(const int* __restrict__ inc_v) {
    int e = blockIdx.x * 256 + threadIdx.x;
    if (e >= N_HEDGES) return;
    int b = g_edge_off[e], en = g_edge_off[e + 1];
    float sum = 0.0f;
    for (int i = b; i < en; i++) sum += g_dvi[inc_v[i]];
    float dei = (en > b) ? 1.0f / (float)(en - b) : 0.0f;
    g_te[e] = dei * sum;
}

__global__ __launch_bounds__(256)
void s_kernel() {
    int v = blockIdx.x * 256 + threadIdx.x;
    if (v >= N_NODES) return;
    int b = g_node_off[v], en = g_node_off[v + 1];
    float sum = 0.0f;
    for (int j = b; j < en; j++) sum += g_te[g_node_edges[j]];
    g_s[v] = g_dvi[v] * sum;
}

__global__ __launch_bounds__(256)
void wt_kernel(const float* __restrict__ W, __half* __restrict__ out, int K, int N) {
    int i = blockIdx.x * 256 + threadIdx.x;
    if (i < K * N) {
        int n = i / K, k = i % K;
        out[i] = __float2half(W[k * N + n]);
    }
}

// Xh[v,:] = dvi(cnt[v]) * X[v,:]  as fp16. Warp per node.
__global__ __launch_bounds__(256)
void x_to_hs_kernel(const float* __restrict__ X) {
    int v = (blockIdx.x * 256 + threadIdx.x) >> 5;
    if (v >= N_NODES) return;
    int lane = threadIdx.x & 31;
    int c = g_dv_cnt[v];
    float dvi = (c > 0) ? rsqrtf((float)c) : 0.0f;
    float4 x = *(const float4*)(X + (size_t)v * C1 + lane * 4);
    uint2 o;
    ((__half2*)&o)[0] = __floats2half2_rn(x.x * dvi, x.y * dvi);
    ((__half2*)&o)[1] = __floats2half2_rn(x.z * dvi, x.w * dvi);
    *(uint2*)(g_Xh + (size_t)v * C1 + lane * 4) = o;
}

// ---------------- gathers: warp/edge(node), 16 lanes x 8ch, 4 incid per half-warp iter ----------------
__device__ __forceinline__ void accum_u4(float* a, uint4 x) {
    const __half2* hx = (const __half2*)&x;
    float2 f0 = __half22float2(hx[0]);
    float2 f1 = __half22float2(hx[1]);
    float2 f2 = __half22float2(hx[2]);
    float2 f3 = __half22float2(hx[3]);
    a[0] += f0.x; a[1] += f0.y; a[2] += f1.x; a[3] += f1.y;
    a[4] += f2.x; a[5] += f2.y; a[6] += f3.x; a[7] += f3.y;
}

__device__ __forceinline__ void gather_rows(float* a, const int* __restrict__ idx,
                                            int b, int e, int half, int li,
                                            const __half* __restrict__ rows) {
    int i = b + half;
    for (; i + 6 < e; i += 8) {
        int u0 = idx[i], u1 = idx[i + 2], u2 = idx[i + 4], u3 = idx[i + 6];
        uint4 x0 = *(const uint4*)(rows + (size_t)u0 * C1 + li * 8);
        uint4 x1 = *(const uint4*)(rows + (size_t)u1 * C1 + li * 8);
        uint4 x2 = *(const uint4*)(rows + (size_t)u2 * C1 + li * 8);
        uint4 x3 = *(const uint4*)(rows + (size_t)u3 * C1 + li * 8);
        accum_u4(a, x0); accum_u4(a, x1); accum_u4(a, x2); accum_u4(a, x3);
    }
    for (; i < e; i += 2) {
        uint4 x = *(const uint4*)(rows + (size_t)idx[i] * C1 + li * 8);
        accum_u4(a, x);
    }
}

// Yeh[e] = (1/deg_e) * sum rows[u]   (rows already carry their dvi factor)
__global__ __launch_bounds__(256)
void edge_agg_kernel(const __half* __restrict__ rows, const int* __restrict__ inc_v) {
    int w = (blockIdx.x * 256 + threadIdx.x) >> 5;
    if (w >= N_HEDGES) return;
    int lane = threadIdx.x & 31;
    int half = lane >> 4, li = lane & 15;
    int b = g_edge_off[w], e = g_edge_off[w + 1];
    float a[8] = {0.f, 0.f, 0.f, 0.f, 0.f, 0.f, 0.f, 0.f};
    gather_rows(a, inc_v, b, e, half, li, rows);
    #pragma unroll
    for (int r = 0; r < 8; r++) a[r] += __shfl_down_sync(0xffffffffu, a[r], 16);
    if (half == 0) {
        float d = (e > b) ? 1.0f / (float)(e - b) : 0.0f;
        uint4 o;
        ((__half2*)&o)[0] = __floats2half2_rn(a[0] * d, a[1] * d);
        ((__half2*)&o)[1] = __floats2half2_rn(a[2] * d, a[3] * d);
        ((__half2*)&o)[2] = __floats2half2_rn(a[4] * d, a[5] * d);
        ((__half2*)&o)[3] = __floats2half2_rn(a[6] * d, a[7] * d);
        *(uint4*)(g_Yeh + (size_t)w * C1 + li * 8) = o;
    }
}

// Xout[v,:] = dvi[v] * sum_e Yeh[e,:]
__global__ __launch_bounds__(256)
void node_agg_h_kernel(__half* __restrict__ Xout) {
    int v = (blockIdx.x * 256 + threadIdx.x) >> 5;
    if (v >= N_NODES) return;
    int lane = threadIdx.x & 31;
    int half = lane >> 4, li = lane & 15;
    int b = g_node_off[v], e = g_node_off[v + 1];
    float a[8] = {0.f, 0.f, 0.f, 0.f, 0.f, 0.f, 0.f, 0.f};
    gather_rows(a, g_node_edges, b, e, half, li, g_Yeh);
    #pragma unroll
    for (int r = 0; r < 8; r++) a[r] += __shfl_down_sync(0xffffffffu, a[r], 16);
    if (half == 0) {
        float d = g_dvi[v];
        uint4 o;
        ((__half2*)&o)[0] = __floats2half2_rn(a[0] * d, a[1] * d);
        ((__half2*)&o)[1] = __floats2half2_rn(a[2] * d, a[3] * d);
        ((__half2*)&o)[2] = __floats2half2_rn(a[4] * d, a[5] * d);
        ((__half2*)&o)[3] = __floats2half2_rn(a[6] * d, a[7] * d);
        *(uint4*)(Xout + (size_t)v * C1 + li * 8) = o;
    }
}

// zfc[v] = sum_c relu(dvi[v]*agg_c + s[v]*b2[c]) * fcW[c]
__global__ __launch_bounds__(256)
void node_agg_final_kernel(const float* __restrict__ b2, const float* __restrict__ fcW) {
    int v = (blockIdx.x * 256 + threadIdx.x) >> 5;
    if (v >= N_NODES) return;
    int lane = threadIdx.x & 31;
    int half = lane >> 4, li = lane & 15;
    int b = g_node_off[v], e = g_node_off[v + 1];
    float a[8] = {0.f, 0.f, 0.f, 0.f, 0.f, 0.f, 0.f, 0.f};
    gather_rows(a, g_node_edges, b, e, half, li, g_Yeh);
    #pragma unroll
    for (int r = 0; r < 8; r++) a[r] += __shfl_down_sync(0xffffffffu, a[r], 16);

    float p = 0.0f;
    if (half == 0) {
        float d  = g_dvi[v];
        float sv = g_s[v];
        float4 bb0 = *(const float4*)(b2 + li * 8);
        float4 bb1 = *(const float4*)(b2 + li * 8 + 4);
        float4 fw0 = *(const float4*)(fcW + li * 8);
        float4 fw1 = *(const float4*)(fcW + li * 8 + 4);
        p += fmaxf(fmaf(d, a[0], sv * bb0.x), 0.f) * fw0.x;
        p += fmaxf(fmaf(d, a[1], sv * bb0.y), 0.f) * fw0.y;
        p += fmaxf(fmaf(d, a[2], sv * bb0.z), 0.f) * fw0.z;
        p += fmaxf(fmaf(d, a[3], sv * bb0.w), 0.f) * fw0.w;
        p += fmaxf(fmaf(d, a[4], sv * bb1.x), 0.f) * fw1.x;
        p += fmaxf(fmaf(d, a[5], sv * bb1.y), 0.f) * fw1.y;
        p += fmaxf(fmaf(d, a[6], sv * bb1.z), 0.f) * fw1.z;
        p += fmaxf(fmaf(d, a[7], sv * bb1.w), 0.f) * fw1.w;
    }
    #pragma unroll
    for (int o = 8; o > 0; o >>= 1) p += __shfl_down_sync(0xffffffffu, p, o);
    if (lane == 0) g_zfc[v] = p;
}

// ---------------- fused GEMM: th = dvi * (relu(X2@W1 + s*b1) @ W2) ----------------
#define FS_X2 69632
#define FS_W2 104448
#define FUSED_SMEM 172032
#define W1S 136
#define X2S 136
#define HS  264
#define W2S 264

__global__ __launch_bounds__(256)
void fused_gemm_kernel(const __half* __restrict__ X2, const __half* __restrict__ W1T,
                       const __half* __restrict__ W2T, int M,
                       const float* __restrict__ s, const float* __restrict__ b1,
                       const float* __restrict__ dvi, __half* __restrict__ th) {
    extern __shared__ char sm[];
    __half* W1s = (__half*)sm;             // also hs
    __half* X2s = (__half*)(sm + FS_X2);
    __half* W2s = (__half*)(sm + FS_W2);

    int tid = threadIdx.x;
    int wid = tid >> 5, lane = tid & 31;
    int warp_m = wid >> 2;
    int warp_n = wid & 3;
    int gid = lane >> 2;
    int tig = lane & 3;
    int blockRow = blockIdx.x * 128;

    #pragma unroll
    for (int t = 0; t < 8; t++) {
        int idx = tid + t * 256;
        int r = idx >> 4, c = (idx & 15) << 3;
        int grow = blockRow + r;
        bool p = grow < M;
        cp_async16(X2s + r * X2S + c, X2 + (size_t)(p ? grow : 0) * C1 + c, p);
    }
    #pragma unroll
    for (int t = 0; t < 16; t++) {
        int idx = tid + t * 256;
        int r = idx >> 4, c = (idx & 15) << 3;
        cp_async16(W1s + r * W1S + c, W1T + (size_t)r * C1 + c, true);
    }
    CP_COMMIT();
    #pragma unroll
    for (int t = 0; t < 16; t++) {
        int idx = tid + t * 256;
        int r = idx >> 5, c = (idx & 31) << 3;
        cp_async16(W2s + r * W2S + c, W2T + (size_t)r * C2 + c, true);
    }
    CP_COMMIT();
    CP_WAIT_1();
    __syncthreads();

    uint32_t hreg[2][4][4][2];
    #pragma unroll
    for (int nh = 0; nh < 2; nh++) {
        float acc[4][4][4];
        #pragma unroll
        for (int i = 0; i < 4; i++)
            #pragma unroll
            for (int j = 0; j < 4; j++)
                #pragma unroll
                for (int r = 0; r < 4; r++) acc[i][j][r] = 0.f;

        #pragma unroll
        for (int k16 = 0; k16 < C1; k16 += 16) {
            uint32_t af[4][4];
            #pragma unroll
            for (int mt = 0; mt < 4; mt++) {
                int rbase = warp_m * 64 + mt * 16;
                const __half* p0 = X2s + (rbase + gid) * X2S + k16 + tig * 2;
                const __half* p1 = X2s + (rbase + gid + 8) * X2S + k16 + tig * 2;
                af[mt][0] = *(const uint32_t*)p0;
                af[mt][1] = *(const uint32_t*)p1;
                af[mt][2] = *(const uint32_t*)(p0 + 8);
                af[mt][3] = *(const uint32_t*)(p1 + 8);
            }
            uint32_t bf[4][2];
            #pragma unroll
            for (int nt = 0; nt < 4; nt++) {
                int nrow = nh * 128 + warp_n * 32 + nt * 8 + gid;
                const __half* p = W1s + nrow * W1S + k16 + tig * 2;
                bf[nt][0] = *(const uint32_t*)p;
                bf[nt][1] = *(const uint32_t*)(p + 8);
            }
            #pragma unroll
            for (int mt = 0; mt < 4; mt++)
                #pragma unroll
                for (int nt = 0; nt < 4; nt++) {
                    asm volatile(
                        "mma.sync.aligned.m16n8k16.row.col.f32.f16.f16.f32 "
                        "{%0,%1,%2,%3}, {%4,%5,%6,%7}, {%8,%9}, {%0,%1,%2,%3};"
                        : "+f"(acc[mt][nt][0]), "+f"(acc[mt][nt][1]),
                          "+f"(acc[mt][nt][2]), "+f"(acc[mt][nt][3])
                        : "r"(af[mt][0]), "r"(af[mt][1]), "r"(af[mt][2]), "r"(af[mt][3]),
                          "r"(bf[nt][0]), "r"(bf[nt][1]));
                }
        }
        #pragma unroll
        for (int mt = 0; mt < 4; mt++) {
            #pragma unroll
            for (int hf = 0; hf < 2; hf++) {
                int row = blockRow + warp_m * 64 + mt * 16 + gid + hf * 8;
                float rs = (row < M) ? s[row] : 0.f;
                #pragma unroll
                for (int nt = 0; nt < 4; nt++) {
                    int col = nh * 128 + warp_n * 32 + nt * 8 + tig * 2;
                    float v0 = fmaxf(fmaf(rs, b1[col],     acc[mt][nt][hf * 2 + 0]), 0.f);
                    float v1 = fmaxf(fmaf(rs, b1[col + 1], acc[mt][nt][hf * 2 + 1]), 0.f);
                    __half2 h2 = __floats2half2_rn(v0, v1);
                    hreg[nh][mt][nt][hf] = *(uint32_t*)&h2;
                }
            }
        }
    }
    __syncthreads();

    #pragma unroll
    for (int nh = 0; nh < 2; nh++)
        #pragma unroll
        for (int mt = 0; mt < 4; mt++)
            #pragma unroll
            for (int hf = 0; hf < 2; hf++) {
                int rloc = warp_m * 64 + mt * 16 + gid + hf * 8;
                #pragma unroll
                for (int nt = 0; nt < 4; nt++) {
                    int col = nh * 128 + warp_n * 32 + nt * 8 + tig * 2;
                    *(uint32_t*)(W1s + rloc * HS + col) = hreg[nh][mt][nt][hf];
                }
            }
    CP_WAIT_0();
    __syncthreads();

    float acc2[4][4][4];
    #pragma unroll
    for (int i = 0; i < 4; i++)
        #pragma unroll
        for (int j = 0; j < 4; j++)
            #pragma unroll
            for (int r = 0; r < 4; r++) acc2[i][j][r] = 0.f;

    #pragma unroll
    for (int k16 = 0; k16 < C2; k16 += 16) {
        uint32_t af[4][4];
        #pragma unroll
        for (int mt = 0; mt < 4; mt++) {
            int rbase = warp_m * 64 + mt * 16;
            const __half* p0 = W1s + (rbase + gid) * HS + k16 + tig * 2;
            const __half* p1 = W1s + (rbase + gid + 8) * HS + k16 + tig * 2;
            af[mt][0] = *(const uint32_t*)p0;
            af[mt][1] = *(const uint32_t*)p1;
            af[mt][2] = *(const uint32_t*)(p0 + 8);
            af[mt][3] = *(const uint32_t*)(p1 + 8);
        }
        uint32_t bf[4][2];
        #pragma unroll
        for (int nt = 0; nt < 4; nt++) {
            int nrow = warp_n * 32 + nt * 8 + gid;
            const __half* p = W2s + nrow * W2S + k16 + tig * 2;
            bf[nt][0] = *(const uint32_t*)p;
            bf[nt][1] = *(const uint32_t*)(p + 8);
        }
        #pragma unroll
        for (int mt = 0; mt < 4; mt++)
            #pragma unroll
            for (int nt = 0; nt < 4; nt++) {
                asm volatile(
                    "mma.sync.aligned.m16n8k16.row.col.f32.f16.f16.f32 "
                    "{%0,%1,%2,%3}, {%4,%5,%6,%7}, {%8,%9}, {%0,%1,%2,%3};"
                    : "+f"(acc2[mt][nt][0]), "+f"(acc2[mt][nt][1]),
                      "+f"(acc2[mt][nt][2]), "+f"(acc2[mt][nt][3])
                    : "r"(af[mt][0]), "r"(af[mt][1]), "r"(af[mt][2]), "r"(af[mt][3]),
                      "r"(bf[nt][0]), "r"(bf[nt][1]));
            }
    }

    #pragma unroll
    for (int mt = 0; mt < 4; mt++) {
        #pragma unroll
        for (int hf = 0; hf < 2; hf++) {
            int row = blockRow + warp_m * 64 + mt * 16 + gid + hf * 8;
            if (row >= M) continue;
            float dv = dvi[row];
            #pragma unroll
            for (int nt = 0; nt < 4; nt++) {
                int col = warp_n * 32 + nt * 8 + tig * 2;
                *(__half2*)(th + (size_t)row * C1 + col) =
                    __floats2half2_rn(acc2[mt][nt][hf * 2 + 0] * dv,
                                      acc2[mt][nt][hf * 2 + 1] * dv);
            }
        }
    }
}

// ---------------- link scoring ----------------
__global__ __launch_bounds__(256)
void link_kernel(const int* __restrict__ link, const float* __restrict__ fcb,
                 float* __restrict__ out) {
    int i = blockIdx.x * 256 + threadIdx.x;
    if (i >= N_LINKS) return;
    int a = link[2 * i], b = link[2 * i + 1];
    float x = (g_zfc[a] + g_zfc[b]) * 0.5f + fcb[0];
    out[i] = 1.0f / (1.0f + __expf(-x));
}

// ---------------- launch ----------------
extern "C" void kernel_launch(void* const* d_in, const int* in_sizes, int n_in,
                              void* d_out, int out_size) {
    const float* X    = (const float*)d_in[0];
    const float* W1   = (const float*)d_in[1];
    const float* b1   = (const float*)d_in[2];
    const float* W2   = (const float*)d_in[3];
    const float* b2   = (const float*)d_in[4];
    const float* fcW  = (const float*)d_in[5];
    const float* fcb  = (const float*)d_in[6];
    const int*   incv = (const int*)d_in[7];
    const int*   ince = (const int*)d_in[8];
    const int*   link = (const int*)d_in[9];
    float* out = (float*)d_out;

    static float*  p_s   = nullptr;
    static float*  p_dvi = nullptr;
    static __half* p_Xh  = nullptr;
    static __half* p_X2h = nullptr;
    static __half* p_th  = nullptr;
    static __half* p_W1T = nullptr;
    static __half* p_W2T = nullptr;
    static cudaStream_t s2 = nullptr, s3 = nullptr;
    static cudaEvent_t evFork = nullptr, evB = nullptr, evCount = nullptr,
                       evC = nullptr, evW2 = nullptr;
    if (!p_s) {
        cudaGetSymbolAddress((void**)&p_s,   g_s);
        cudaGetSymbolAddress((void**)&p_dvi, g_dvi);
        cudaGetSymbolAddress((void**)&p_Xh,  g_Xh);
        cudaGetSymbolAddress((void**)&p_X2h, g_X2h);
        cudaGetSymbolAddress((void**)&p_th,  g_th);
        cudaGetSymbolAddress((void**)&p_W1T, g_W1T);
        cudaGetSymbolAddress((void**)&p_W2T, g_W2T);
        cudaStreamCreateWithFlags(&s2, cudaStreamNonBlocking);
        cudaStreamCreateWithFlags(&s3, cudaStreamNonBlocking);
        cudaEventCreateWithFlags(&evFork,  cudaEventDisableTiming);
        cudaEventCreateWithFlags(&evB,     cudaEventDisableTiming);
        cudaEventCreateWithFlags(&evCount, cudaEventDisableTiming);
        cudaEventCreateWithFlags(&evC,     cudaEventDisableTiming);
        cudaEventCreateWithFlags(&evW2,    cudaEventDisableTiming);
        cudaFuncSetAttribute(fused_gemm_kernel,
                             cudaFuncAttributeMaxDynamicSharedMemorySize, FUSED_SMEM);
    }

    const int TPB = 256;
    int inc_blocks    = (N_INC + TPB - 1) / TPB;
    int node_blocks   = (N_NODES + TPB - 1) / TPB;
    int edge_blocks   = (N_HEDGES + 1 + TPB - 1) / TPB;
    int warp_blocks_e = (N_HEDGES * 32 + TPB - 1) / TPB;
    int warp_blocks_n = (N_NODES * 32 + TPB - 1) / TPB;
    int wt_blocks     = (C1 * C2 + TPB - 1) / TPB;
    int gemm_rows     = (N_NODES + 127) / 128;   // 782

    // ---- branch B (s2): edge offsets + weight transposes ----
    cudaEventRecord(evFork, 0);
    cudaStreamWaitEvent(s2, evFork, 0);
    edge_off_kernel<<<edge_blocks, TPB, 0, s2>>>(ince);
    wt_kernel<<<wt_blocks, TPB, 0, s2>>>(W1, p_W1T, C1, C2);
    cudaEventRecord(evB, s2);
    wt_kernel<<<wt_blocks, TPB, 0, s2>>>(W2, p_W2T, C2, C1);
    cudaEventRecord(evW2, s2);

    // ---- main: counts -> pre-scaled fp16 X -> edge_agg1 ----
    zero_counts_kernel<<<node_blocks, TPB>>>();
    count_kernel<<<inc_blocks, TPB>>>(incv);
    cudaEventRecord(evCount, 0);
    x_to_hs_kernel<<<warp_blocks_n, TPB>>>(X);
    cudaStreamWaitEvent(0, evB, 0);
    edge_agg_kernel<<<warp_blocks_e, TPB>>>(p_Xh, incv);

    // ---- branch C (s3): scan + csr + te + s, hidden under edge_agg1 ----
    cudaStreamWaitEvent(s3, evCount, 0);
    cudaStreamWaitEvent(s3, evB, 0);
    node_scan_phase1<<<SCAN_BLOCKS, TPB, 0, s3>>>();
    node_scan_phase2<<<1, 128, 0, s3>>>();
    node_scan_phase3<<<SCAN_BLOCKS, TPB, 0, s3>>>();
    build_csr_kernel<<<inc_blocks, TPB, 0, s3>>>(incv, ince);
    te_kernel<<<node_blocks, TPB, 0, s3>>>(incv);
    s_kernel<<<node_blocks, TPB, 0, s3>>>();
    cudaEventRecord(evC, s3);

    // ---- main: node agg, fused GEMM, layer 2, output ----
    cudaStreamWaitEvent(0, evC, 0);
    node_agg_h_kernel<<<warp_blocks_n, TPB>>>(p_X2h);
    cudaStreamWaitEvent(0, evW2, 0);
    fused_gemm_kernel<<<gemm_rows, 256, FUSED_SMEM>>>(p_X2h, p_W1T, p_W2T,
                                                      N_NODES, p_s, b1, p_dvi, p_th);
    edge_agg_kernel<<<warp_blocks_e, TPB>>>(p_th, incv);
    node_agg_final_kernel<<<warp_blocks_n, TPB>>>(b2, fcW);
    link_kernel<<<(N_LINKS + TPB - 1) / TPB, TPB>>>(link, fcb, out);
    (void)in_sizes; (void)n_in; (void)out_size;
}